// round 11
// baseline (speedup 1.0000x reference)
#include <cuda_runtime.h>
#include <cuda_bf16.h>
#include <cstdint>

#define NN   50000
#define EE   800000
#define HH   4
#define HUU  128

// Scratch (device globals; allocation-free rule)
__device__ __align__(16) float g_q[NN * HUU];
__device__ __align__(16) float g_k[NN * HUU];
__device__ __align__(16) float g_v[NN * HUU];
__device__ __align__(16) float g_kw[NN * 256];
__device__ int g_rowptr[NN + 1];
__device__ __align__(16) __nv_bfloat16 g_Xhi[NN * 128];
__device__ __align__(16) __nv_bfloat16 g_Xlo[NN * 128];
__device__ __align__(16) __nv_bfloat16 g_Bhi[5 * 128 * 128];  // [ntile][n][k]
__device__ __align__(16) __nv_bfloat16 g_Blo[5 * 128 * 128];
__device__ float g_bias[640];

static __device__ __forceinline__ float dot4(float4 a, float4 b) {
    return a.x * b.x + a.y * b.y + a.z * b.z + a.w * b.w;
}
static __device__ __forceinline__ unsigned smem_u32(const void* p) {
    unsigned a;
    asm("{ .reg .u64 t; cvta.to.shared.u64 t, %1; cvt.u32.u64 %0, t; }" : "=r"(a) : "l"(p));
    return a;
}
static __device__ __forceinline__ void ldm4(unsigned* r, unsigned addr) {
    asm volatile("ldmatrix.sync.aligned.m8n8.x4.shared.b16 {%0,%1,%2,%3}, [%4];"
        : "=r"(r[0]), "=r"(r[1]), "=r"(r[2]), "=r"(r[3]) : "r"(addr));
}
static __device__ __forceinline__ void mma16816(float* c, const unsigned* a,
                                                unsigned b0, unsigned b1) {
    asm volatile("mma.sync.aligned.m16n8k16.row.col.f32.bf16.bf16.f32 "
        "{%0,%1,%2,%3}, {%4,%5,%6,%7}, {%8,%9}, {%0,%1,%2,%3};"
        : "+f"(c[0]), "+f"(c[1]), "+f"(c[2]), "+f"(c[3])
        : "r"(a[0]), "r"(a[1]), "r"(a[2]), "r"(a[3]), "r"(b0), "r"(b1));
}

// ---------- setup: X -> bf16 hi/lo ----------
__global__ void convx_kernel(const float* __restrict__ X, int total4)
{
    int i = blockIdx.x * blockDim.x + threadIdx.x;
    if (i >= total4) return;
    float4 x = __ldg(reinterpret_cast<const float4*>(X) + i);
    __nv_bfloat16 h0 = __float2bfloat16(x.x), h1 = __float2bfloat16(x.y);
    __nv_bfloat16 h2 = __float2bfloat16(x.z), h3 = __float2bfloat16(x.w);
    __nv_bfloat16 l0 = __float2bfloat16(x.x - __bfloat162float(h0));
    __nv_bfloat16 l1 = __float2bfloat16(x.y - __bfloat162float(h1));
    __nv_bfloat16 l2 = __float2bfloat16(x.z - __bfloat162float(h2));
    __nv_bfloat16 l3 = __float2bfloat16(x.w - __bfloat162float(h3));
    g_Xhi[i*4+0]=h0; g_Xhi[i*4+1]=h1; g_Xhi[i*4+2]=h2; g_Xhi[i*4+3]=h3;
    g_Xlo[i*4+0]=l0; g_Xlo[i*4+1]=l1; g_Xlo[i*4+2]=l2; g_Xlo[i*4+3]=l3;
}

// ---------- setup: B tiles (Wq | Wk | Wv | Wfused(2 tiles)), layout [ntile][n][k] ----------
__global__ void setupb_kernel(const float* __restrict__ Wq, const float* __restrict__ Wk,
                              const float* __restrict__ Wv, const float* __restrict__ We)
{
    int idx = blockIdx.x * blockDim.x + threadIdx.x;
    if (idx >= 5 * 128 * 128) return;
    int ntile = idx >> 14;
    int r = idx & 16383;
    int nloc = r >> 7, k = r & 127;
    float w;
    if (ntile == 0)      w = __ldg(&Wq[k * 128 + nloc]);
    else if (ntile == 1) w = __ldg(&Wk[k * 128 + nloc]);
    else if (ntile == 2) w = __ldg(&Wv[k * 128 + nloc]);
    else {
        int col = (ntile - 3) * 128 + nloc;
        int h = col >> 6, dd = col & 63;
        w = 0.f;
        #pragma unroll 8
        for (int u = 0; u < 32; u++)
            w += __ldg(&Wk[k * 128 + h * 32 + u]) * __ldg(&We[dd * 128 + h * 32 + u]);
    }
    __nv_bfloat16 hi = __float2bfloat16(w);
    __nv_bfloat16 lo = __float2bfloat16(w - __bfloat162float(hi));
    g_Bhi[idx] = hi;
    g_Blo[idx] = lo;
}

// ---------- setup: fused biases ----------
__global__ void setupbias_kernel(const float* __restrict__ bq, const float* __restrict__ bk,
                                 const float* __restrict__ bv, const float* __restrict__ be,
                                 const float* __restrict__ We)
{
    int idx = blockIdx.x * blockDim.x + threadIdx.x;
    if (idx >= 640) return;
    float b;
    if (idx < 128)       b = __ldg(&bq[idx]) + __ldg(&be[idx]);
    else if (idx < 256)  b = __ldg(&bk[idx - 128]);
    else if (idx < 384)  b = __ldg(&bv[idx - 256]);
    else {
        int col = idx - 384;
        int h = col >> 6, dd = col & 63;
        b = 0.f;
        for (int u = 0; u < 32; u++)
            b += __ldg(&We[dd * 128 + h * 32 + u]) * __ldg(&bk[h * 32 + u]);
    }
    g_bias[idx] = b;
}

// ---------- CSR row pointers: scatter from sorted src (thread-per-edge) ----------
__global__ void rowptr_kernel(const int* __restrict__ src, int n, int e)
{
    int i = blockIdx.x * blockDim.x + threadIdx.x;
    if (i >= e) return;
    const int s = __ldg(&src[i]);
    if (i == 0) {
        for (int v = 0; v <= s; v++) g_rowptr[v] = 0;
    } else {
        const int prev = __ldg(&src[i - 1]);
        for (int v = prev + 1; v <= s; v++) g_rowptr[v] = i;
    }
    if (i == e - 1) {
        for (int v = s + 1; v <= n; v++) g_rowptr[v] = e;
    }
}

// ---------- mma.sync GEMM: A staged once, 5 n-tiles looped inside the block ----------
// D = Ahi*Bhi + Ahi*Blo + Alo*Bhi (lo*lo dropped, ~2^-16). 8 warps: 4 m x 2 n.
#define LDB 40    // B chunk: padded bf16 per row (80B stride, conflict-free)
#define LDA2 136  // A full-k: padded bf16 per row (272B stride = 17 odd slots, conflict-free)
#define SA_HI 0
#define SA_LO 34816
#define SB_HI 69632
#define SB_LO 79872
#define GSM_TOTAL 90112

__global__ void __launch_bounds__(256, 2) gemm_kernel(int n)
{
    extern __shared__ __align__(16) char gsm[];
    __nv_bfloat16* sAhi = reinterpret_cast<__nv_bfloat16*>(gsm + SA_HI);
    __nv_bfloat16* sAlo = reinterpret_cast<__nv_bfloat16*>(gsm + SA_LO);
    __nv_bfloat16* sBhi = reinterpret_cast<__nv_bfloat16*>(gsm + SB_HI);
    __nv_bfloat16* sBlo = reinterpret_cast<__nv_bfloat16*>(gsm + SB_LO);

    const int tid = threadIdx.x;
    const int wid = tid >> 5, lane = tid & 31;
    const int row0 = blockIdx.x * 128;
    const int m_off = (wid & 3) * 32;
    const int n_off = (wid >> 2) * 64;

    const unsigned aAhi = smem_u32(sAhi), aAlo = smem_u32(sAlo);
    const unsigned aBhi = smem_u32(sBhi), aBlo = smem_u32(sBlo);

    // stage full A (128 rows x 128 k, hi/lo) once
    // 1024 iters x 16 elements = 128 x 128  (R10 bug: bound was 2048 -> OOB)
    for (int i = tid; i < 1024; i += 256) {
        const int row = i >> 3, cc = (i & 7) * 16;
        const int gr = row0 + row;
        uint4 vh0 = make_uint4(0u,0u,0u,0u), vh1 = vh0, vl0 = vh0, vl1 = vh0;
        if (gr < n) {
            vh0 = *reinterpret_cast<const uint4*>(&g_Xhi[(size_t)gr * 128 + cc]);
            vh1 = *reinterpret_cast<const uint4*>(&g_Xhi[(size_t)gr * 128 + cc + 8]);
            vl0 = *reinterpret_cast<const uint4*>(&g_Xlo[(size_t)gr * 128 + cc]);
            vl1 = *reinterpret_cast<const uint4*>(&g_Xlo[(size_t)gr * 128 + cc + 8]);
        }
        *reinterpret_cast<uint4*>(&sAhi[row * LDA2 + cc])     = vh0;
        *reinterpret_cast<uint4*>(&sAhi[row * LDA2 + cc + 8]) = vh1;
        *reinterpret_cast<uint4*>(&sAlo[row * LDA2 + cc])     = vl0;
        *reinterpret_cast<uint4*>(&sAlo[row * LDA2 + cc + 8]) = vl1;
    }

    // ldmatrix lane offsets (element units)
    const unsigned a_lm = (unsigned)((lane & 15) * LDA2 + (lane >> 4) * 8);
    const unsigned b_lm = (unsigned)((((lane >> 4) << 3) + (lane & 7)) * LDB
                                     + ((lane >> 3) & 1) * 8);

    #pragma unroll 1
    for (int nt = 0; nt < 5; nt++) {
        float acc[2][8][4];
        #pragma unroll
        for (int mf = 0; mf < 2; mf++)
            #pragma unroll
            for (int nf = 0; nf < 8; nf++)
                #pragma unroll
                for (int j = 0; j < 4; j++) acc[mf][nf][j] = 0.f;

        #pragma unroll 1
        for (int c = 0; c < 4; c++) {
            const int k0 = c * 32;
            __syncthreads();   // protect sB overwrite (also orders sA on first pass)
            for (int i = tid; i < 512; i += 256) {
                const int row = i >> 2, cc = (i & 3) * 8;
                const uint4 bh = *reinterpret_cast<const uint4*>(
                    &g_Bhi[(size_t)nt * 16384 + row * 128 + k0 + cc]);
                const uint4 bl = *reinterpret_cast<const uint4*>(
                    &g_Blo[(size_t)nt * 16384 + row * 128 + k0 + cc]);
                *reinterpret_cast<uint4*>(&sBhi[row * LDB + cc]) = bh;
                *reinterpret_cast<uint4*>(&sBlo[row * LDB + cc]) = bl;
            }
            __syncthreads();

            #pragma unroll
            for (int ks = 0; ks < 2; ks++) {
                const int kk = k0 + ks * 16;
                unsigned ahi[2][4], alo[2][4];
                #pragma unroll
                for (int mf = 0; mf < 2; mf++) {
                    const unsigned off = ((m_off + mf * 16) * LDA2 + kk) * 2 + a_lm * 2;
                    ldm4(ahi[mf], aAhi + off);
                    ldm4(alo[mf], aAlo + off);
                }
                #pragma unroll
                for (int np = 0; np < 4; np++) {
                    unsigned bhi[4], blo[4];
                    const unsigned off = ((n_off + np * 16) * LDB + ks * 16) * 2 + b_lm * 2;
                    ldm4(bhi, aBhi + off);
                    ldm4(blo, aBlo + off);
                    #pragma unroll
                    for (int mf = 0; mf < 2; mf++) {
                        float* c0 = acc[mf][np * 2];
                        float* c1 = acc[mf][np * 2 + 1];
                        mma16816(c0, ahi[mf], bhi[0], bhi[1]);
                        mma16816(c0, ahi[mf], blo[0], blo[1]);
                        mma16816(c0, alo[mf], bhi[0], bhi[1]);
                        mma16816(c1, ahi[mf], bhi[2], bhi[3]);
                        mma16816(c1, ahi[mf], blo[2], blo[3]);
                        mma16816(c1, alo[mf], bhi[2], bhi[3]);
                    }
                }
            }
        }

        // epilogue: direct float2 stores with bias
        float* outp;
        int stride, cbase;
        if (nt == 0)      { outp = g_q;  stride = 128; cbase = 0; }
        else if (nt == 1) { outp = g_k;  stride = 128; cbase = 0; }
        else if (nt == 2) { outp = g_v;  stride = 128; cbase = 0; }
        else if (nt == 3) { outp = g_kw; stride = 256; cbase = 0; }
        else              { outp = g_kw; stride = 256; cbase = 128; }

        #pragma unroll
        for (int mf = 0; mf < 2; mf++) {
            #pragma unroll
            for (int nf = 0; nf < 8; nf++) {
                const int r = m_off + mf * 16 + (lane >> 2);
                const int col = n_off + nf * 8 + (lane & 3) * 2;
                const float b0 = __ldg(&g_bias[nt * 128 + col]);
                const float b1 = __ldg(&g_bias[nt * 128 + col + 1]);
                const int gr0 = row0 + r, gr1 = gr0 + 8;
                if (gr0 < n) {
                    float2 v0 = make_float2(acc[mf][nf][0] + b0, acc[mf][nf][1] + b1);
                    *reinterpret_cast<float2*>(&outp[(size_t)gr0 * stride + cbase + col]) = v0;
                }
                if (gr1 < n) {
                    float2 v1 = make_float2(acc[mf][nf][2] + b0, acc[mf][nf][3] + b1);
                    *reinterpret_cast<float2*>(&outp[(size_t)gr1 * stride + cbase + col]) = v1;
                }
            }
        }
    }
}

// ---------- fused scores + softmax + V-agg + output GEMM; 4-edge unroll ----------
__global__ __launch_bounds__(256) void attn_kernel(
    const int* __restrict__ dst, const float* __restrict__ ef,
    const float* __restrict__ Wo, const float* __restrict__ bo,
    float* __restrict__ out, int n)
{
    __shared__ float att_s[8][128];
    const int wid = threadIdx.x >> 5;
    const int lane = threadIdx.x & 31;
    const int node = blockIdx.x * 8 + wid;
    if (node >= n) return;

    const int h = lane >> 3, u8 = lane & 7;
    const float4* k4p  = reinterpret_cast<const float4*>(g_k);
    const float4* kw4p = reinterpret_cast<const float4*>(g_kw);
    const float4* v4p  = reinterpret_cast<const float4*>(g_v);
    const float4* ef4p = reinterpret_cast<const float4*>(ef);

    const float4 q4 = __ldg(reinterpret_cast<const float4*>(g_q) + (size_t)node * 32 + lane);

    float4 acc4 = make_float4(0.f, 0.f, 0.f, 0.f);
    float sden = 0.f;

    int e = g_rowptr[node];
    const int end = g_rowptr[node + 1];

    for (; e + 4 <= end; e += 4) {
        int dd[4];
        float4 kk[4], wa[4], wb[4], fa[4], fb[4], vv[4];
        #pragma unroll
        for (int j = 0; j < 4; j++) dd[j] = __ldcs(&dst[e + j]);
        #pragma unroll
        for (int j = 0; j < 4; j++) {
            kk[j] = __ldg(&k4p[(size_t)dd[j] * 32 + lane]);
            wa[j] = __ldg(&kw4p[(size_t)dd[j] * 64 + h * 16 + u8 * 2]);
            wb[j] = __ldg(&kw4p[(size_t)dd[j] * 64 + h * 16 + u8 * 2 + 1]);
            fa[j] = __ldcs(&ef4p[(size_t)(e + j) * 16 + u8 * 2]);
            fb[j] = __ldcs(&ef4p[(size_t)(e + j) * 16 + u8 * 2 + 1]);
            vv[j] = __ldg(&v4p[(size_t)dd[j] * 32 + lane]);
        }
        float p[4];
        #pragma unroll
        for (int j = 0; j < 4; j++)
            p[j] = dot4(q4, kk[j]) + dot4(fa[j], wa[j]) + dot4(fb[j], wb[j]);
        #pragma unroll
        for (int off = 4; off; off >>= 1)
            #pragma unroll
            for (int j = 0; j < 4; j++)
                p[j] += __shfl_xor_sync(0xffffffffu, p[j], off);
        #pragma unroll
        for (int j = 0; j < 4; j++) {
            const float w = __expf(p[j]);
            sden += w;
            acc4.x += w * vv[j].x;
            acc4.y += w * vv[j].y;
            acc4.z += w * vv[j].z;
            acc4.w += w * vv[j].w;
        }
    }
    for (; e < end; e++) {  // tail (<=3)
        const int d0 = __ldcs(&dst[e]);
        const float4 k0  = __ldg(&k4p[(size_t)d0 * 32 + lane]);
        const float4 w00 = __ldg(&kw4p[(size_t)d0 * 64 + h * 16 + u8 * 2]);
        const float4 w01 = __ldg(&kw4p[(size_t)d0 * 64 + h * 16 + u8 * 2 + 1]);
        const float4 f00 = __ldcs(&ef4p[(size_t)e * 16 + u8 * 2]);
        const float4 f01 = __ldcs(&ef4p[(size_t)e * 16 + u8 * 2 + 1]);
        const float4 v0  = __ldg(&v4p[(size_t)d0 * 32 + lane]);

        float p0 = dot4(q4, k0) + dot4(f00, w00) + dot4(f01, w01);
        #pragma unroll
        for (int off = 4; off; off >>= 1)
            p0 += __shfl_xor_sync(0xffffffffu, p0, off);
        const float w0 = __expf(p0);
        sden += w0;
        acc4.x += w0 * v0.x;
        acc4.y += w0 * v0.y;
        acc4.z += w0 * v0.z;
        acc4.w += w0 * v0.w;
    }

    const float inv = (sden > 0.f) ? (1.0f / sden) : 0.f;
    float4* as4 = reinterpret_cast<float4*>(&att_s[wid][0]);
    as4[lane] = make_float4(acc4.x * inv, acc4.y * inv, acc4.z * inv, acc4.w * inv);
    __syncwarp();

    float o = __ldg(&bo[lane]);
    #pragma unroll 8
    for (int i = 0; i < 128; i++)
        o += att_s[wid][i] * __ldg(&Wo[(size_t)i * 32 + lane]);
    out[(size_t)node * 32 + lane] = fmaxf(o, 0.0f);
}

extern "C" void kernel_launch(void* const* d_in, const int* in_sizes, int n_in,
                              void* d_out, int out_size)
{
    const float* X  = (const float*)d_in[0];
    const int*   ei = (const int*)d_in[1];
    const float* ef = (const float*)d_in[2];
    const float* Wq = (const float*)d_in[3];
    const float* bq = (const float*)d_in[4];
    const float* Wk = (const float*)d_in[5];
    const float* bk = (const float*)d_in[6];
    const float* Wv = (const float*)d_in[7];
    const float* bv = (const float*)d_in[8];
    const float* We = (const float*)d_in[9];
    const float* be = (const float*)d_in[10];
    const float* Wo = (const float*)d_in[11];
    const float* bo = (const float*)d_in[12];
    float* out = (float*)d_out;

    const int n = in_sizes[0] / HUU;
    const int e = in_sizes[1] / 2;
    const int* src = ei;
    const int* dst = ei + e;

    cudaFuncSetAttribute(gemm_kernel, cudaFuncAttributeMaxDynamicSharedMemorySize, GSM_TOTAL);

    const int total4 = (n * 128) / 4;
    convx_kernel<<<(total4 + 255) / 256, 256>>>(X, total4);
    setupb_kernel<<<(5 * 128 * 128 + 255) / 256, 256>>>(Wq, Wk, Wv, We);
    setupbias_kernel<<<3, 256>>>(bq, bk, bv, be, We);
    rowptr_kernel<<<(e + 255) / 256, 256>>>(src, n, e);
    gemm_kernel<<<(n + 127) / 128, 256, GSM_TOTAL>>>(n);
    attn_kernel<<<(n + 7) / 8, 256>>>(dst, ef, Wo, bo, out, n);
}